// round 13
// baseline (speedup 1.0000x reference)
#include <cuda_runtime.h>

#define E_TOTAL 1600000
#define N_NODES 50000

#define FSCALE     0.17677669529663687f  // 1/sqrt(32)
#define FINV_SQRT3 0.57735026918962576f  // 1/sqrt(3)

#define SCAN_B   512
#define SCAN_NB  ((N_NODES + SCAN_B - 1) / SCAN_B)   // 98

__device__ int    g_counts[N_NODES];
__device__ int    g_cursor[N_NODES];
__device__ int    g_offsets[N_NODES + 1];
__device__ int    g_scantmp[N_NODES];
__device__ int    g_bsums[SCAN_NB];
__device__ int    g_bbase[SCAN_NB];
__device__ int    g_sender[E_TOTAL];            // slot -> sender
__device__ float4 g_rec[(size_t)E_TOTAL * 3];   // slot -> {h0..3, h4..7, ef}
__device__ float4 g_nodes4[N_NODES * 8];        // node -> 8 x {s_m, v_m0, v_m1, v_m2}

__global__ void k_zero_counts() {
    int i = blockIdx.x * blockDim.x + threadIdx.x;
    if (i < N_NODES) g_counts[i] = 0;
}

// Transpose node_feats rows into per-m float4 {s, v0, v1, v2}
__global__ void k_prep_nodes(const float* __restrict__ node_feats) {
    int i = blockIdx.x * blockDim.x + threadIdx.x;   // node*8 + m
    if (i >= N_NODES * 8) return;
    int node = i >> 3;
    int m    = i & 7;
    const float* nf = node_feats + node * 32;
    g_nodes4[i] = make_float4(__ldg(nf + m),
                              __ldg(nf + 8 + 3 * m),
                              __ldg(nf + 9 + 3 * m),
                              __ldg(nf + 10 + 3 * m));
}

// Vectorized: 4 edges per thread (E_TOTAL % 4 == 0)
__global__ void k_count(const int4* __restrict__ receivers4) {
    int i = blockIdx.x * blockDim.x + threadIdx.x;
    if (i < E_TOTAL / 4) {
        int4 r = __ldg(&receivers4[i]);
        atomicAdd(&g_counts[r.x], 1);
        atomicAdd(&g_counts[r.y], 1);
        atomicAdd(&g_counts[r.z], 1);
        atomicAdd(&g_counts[r.w], 1);
    }
}

// Pass 1: per-block inclusive scan of counts
__global__ __launch_bounds__(SCAN_B) void k_scan1() {
    __shared__ int sh[SCAN_B];
    int t   = threadIdx.x;
    int idx = blockIdx.x * SCAN_B + t;
    int v   = (idx < N_NODES) ? g_counts[idx] : 0;
    sh[t] = v;
    __syncthreads();
    for (int off = 1; off < SCAN_B; off <<= 1) {
        int u = (t >= off) ? sh[t - off] : 0;
        __syncthreads();
        sh[t] += u;
        __syncthreads();
    }
    if (idx < N_NODES) g_scantmp[idx] = sh[t];
    if (t == SCAN_B - 1) g_bsums[blockIdx.x] = sh[t];
}

// Pass 2: single small block scans the 98 block sums -> exclusive bases
__global__ __launch_bounds__(128) void k_scan2() {
    __shared__ int sh[128];
    int t = threadIdx.x;
    int v = (t < SCAN_NB) ? g_bsums[t] : 0;
    sh[t] = v;
    __syncthreads();
    for (int off = 1; off < 128; off <<= 1) {
        int u = (t >= off) ? sh[t - off] : 0;
        __syncthreads();
        sh[t] += u;
        __syncthreads();
    }
    if (t < SCAN_NB) g_bbase[t] = sh[t] - v;   // exclusive base
    if (t == SCAN_NB - 1) g_offsets[N_NODES] = sh[t];
}

// Pass 3: global exclusive offsets + cursor
__global__ __launch_bounds__(SCAN_B) void k_scan3() {
    int idx = blockIdx.x * SCAN_B + threadIdx.x;
    if (idx < N_NODES) {
        int off = g_bbase[blockIdx.x] + g_scantmp[idx] - g_counts[idx];
        g_offsets[idx] = off;
        g_cursor[idx]  = off;
    }
}

// Fused fill + hidden MLP: coalesced reads in edge order, scattered 52B writes.
__global__ __launch_bounds__(256) void k_fill_hidden(
    const int*    __restrict__ senders,
    const int*    __restrict__ receivers,
    const float4* __restrict__ radial,
    const float4* __restrict__ edge_features,
    const float*  __restrict__ w1)
{
    __shared__ float sw1[64];
    int t = threadIdx.x;
    if (t < 64) sw1[t] = w1[t];
    __syncthreads();

    int e = blockIdx.x * 256 + t;
    if (e >= E_TOTAL) return;

    float4 r0 = __ldg(&radial[2 * e]);
    float4 r1 = __ldg(&radial[2 * e + 1]);
    float4 ef = __ldg(&edge_features[e]);
    int   snd = __ldg(&senders[e]);
    int   rcv = __ldg(&receivers[e]);

    float r[8] = {r0.x, r0.y, r0.z, r0.w, r1.x, r1.y, r1.z, r1.w};
    float h[8];
    #pragma unroll
    for (int j = 0; j < 8; j++) {
        float acc = 0.f;
        #pragma unroll
        for (int i = 0; i < 8; i++) acc = fmaf(r[i], sw1[i * 8 + j], acc);
        h[j] = acc * (FSCALE / (1.f + __expf(-acc)));
    }

    int pos = atomicAdd(&g_cursor[rcv], 1);
    g_sender[pos]        = snd;
    g_rec[3 * pos]       = make_float4(h[0], h[1], h[2], h[3]);
    g_rec[3 * pos + 1]   = make_float4(h[4], h[5], h[6], h[7]);
    g_rec[3 * pos + 2]   = ef;
}

// One block (8 warps = 256 thr) per node; warp takes 1/8 of segment.
// Lane l (<24) owns scal[l], vec[l][0..2]. 5 loads/edge, no shuffles.
#define EDGE_BODY(KK)                                                         \
    {                                                                         \
        int snd = g_sender[(KK)];                                             \
        float4 nd = g_nodes4[snd * 8 + mm];                                   \
        float4 h0 = g_rec[3 * (KK)];                                          \
        float4 h1 = g_rec[3 * (KK) + 1];                                      \
        float4 ef = g_rec[3 * (KK) + 2];                                      \
        float s = nd.x, v0 = nd.y, v1 = nd.z, v2 = nd.w;                      \
        float e0 = ef.x, e1x = ef.y, e1y = ef.z, e1z = ef.w;                  \
        float wa, wb;                                                         \
        wa = fmaf(h0.x, w2A[0], fmaf(h0.y, w2A[1],                            \
             fmaf(h0.z, w2A[2], h0.w * w2A[3])));                             \
        wa = fmaf(h1.x, w2A[4], fmaf(h1.y, w2A[5],                            \
             fmaf(h1.z, w2A[6], fmaf(h1.w, w2A[7], wa))));                    \
        wb = fmaf(h0.x, w2B[0], fmaf(h0.y, w2B[1],                            \
             fmaf(h0.z, w2B[2], h0.w * w2B[3])));                             \
        wb = fmaf(h1.x, w2B[4], fmaf(h1.y, w2B[5],                            \
             fmaf(h1.z, w2B[6], fmaf(h1.w, w2B[7], wb))));                    \
        float eS   = g0 ? 1.f : (g1 ? e0 : 0.f);                              \
        float dsel = g2 ? 1.f : 0.f;                                          \
        float dot  = fmaf(v0, e1x, fmaf(v1, e1y, v2 * e1z));                  \
        float scal_inner = fmaf(s, eS, dot * dsel);                           \
        float fV  = g0 ? 1.f : (g2 ? e0 : 0.f);                               \
        float sfs = s * fS;                                                   \
        float i0 = fmaf(v0, fV, sfs * e1x);                                   \
        float i1 = fmaf(v1, fV, sfs * e1y);                                   \
        float i2 = fmaf(v2, fV, sfs * e1z);                                   \
        acc_s  = fmaf(scal_inner, wa, acc_s);                                 \
        acc_v0 = fmaf(i0, wb, acc_v0);                                        \
        acc_v1 = fmaf(i1, wb, acc_v1);                                        \
        acc_v2 = fmaf(i2, wb, acc_v2);                                        \
    }

__global__ __launch_bounds__(256) void k_gather(
    const float* __restrict__ w2,
    float*       __restrict__ out)
{
    __shared__ float red[8][96];

    int node = blockIdx.x;
    int lane = threadIdx.x & 31;
    int wi   = threadIdx.x >> 5;   // 0..7
    int mm   = lane & 7;

    bool g0 = lane < 8;
    bool g1 = (lane >= 8) && (lane < 16);
    bool g2 = (lane >= 16) && (lane < 24);
    int  cA = (lane < 24) ? lane : 0;
    float fS = g1 ? 1.f : 0.f;
    float sA = g2 ? FINV_SQRT3 : 1.f;

    float w2A[8], w2B[8];
    #pragma unroll
    for (int j = 0; j < 8; j++) {
        w2A[j] = __ldg(&w2[j * 48 + cA]) * sA;
        w2B[j] = __ldg(&w2[j * 48 + 24 + cA]);
    }

    int beg = g_offsets[node];
    int end = g_offsets[node + 1];
    int len = end - beg;
    int lo  = beg + (len * wi)       / 8;
    int hi  = beg + (len * (wi + 1)) / 8;

    float acc_s = 0.f, acc_v0 = 0.f, acc_v1 = 0.f, acc_v2 = 0.f;

    int k = lo;
    #pragma unroll 1
    for (; k + 1 < hi; k += 2) {
        EDGE_BODY(k)
        EDGE_BODY(k + 1)
    }
    if (k < hi) EDGE_BODY(k)

    if (lane < 24) {
        red[wi][lane]              = acc_s;
        red[wi][24 + 3 * lane]     = acc_v0;
        red[wi][24 + 3 * lane + 1] = acc_v1;
        red[wi][24 + 3 * lane + 2] = acc_v2;
    }
    __syncthreads();

    int t = threadIdx.x;
    if (t < 96) {
        float sum = red[0][t] + red[1][t] + red[2][t] + red[3][t]
                  + red[4][t] + red[5][t] + red[6][t] + red[7][t];
        out[(size_t)node * 96 + t] = sum;
    }
}

extern "C" void kernel_launch(void* const* d_in, const int* in_sizes, int n_in,
                              void* d_out, int out_size) {
    const float*  node_feats    = (const float*)d_in[0];
    const float4* edge_features = (const float4*)d_in[1];
    const float4* radial        = (const float4*)d_in[2];
    const float*  w1            = (const float*)d_in[3];
    const float*  w2            = (const float*)d_in[4];
    const int*    senders       = (const int*)d_in[5];
    const int*    receivers     = (const int*)d_in[6];
    float* out = (float*)d_out;

    k_zero_counts<<<(N_NODES + 511) / 512, 512>>>();
    k_prep_nodes<<<(N_NODES * 8 + 255) / 256, 256>>>(node_feats);
    k_count<<<(E_TOTAL / 4 + 255) / 256, 256>>>((const int4*)receivers);
    k_scan1<<<SCAN_NB, SCAN_B>>>();
    k_scan2<<<1, 128>>>();
    k_scan3<<<SCAN_NB, SCAN_B>>>();
    k_fill_hidden<<<(E_TOTAL + 255) / 256, 256>>>(senders, receivers, radial,
                                                  edge_features, w1);
    k_gather<<<N_NODES, 256>>>(w2, out);
}

// round 14
// speedup vs baseline: 1.2776x; 1.2776x over previous
#include <cuda_runtime.h>

#define E_TOTAL 1600000
#define N_NODES 50000

#define FSCALE     0.17677669529663687f  // 1/sqrt(32)
#define FINV_SQRT3 0.57735026918962576f  // 1/sqrt(3)

#define SCAN_B   512
#define SCAN_NB  ((N_NODES + SCAN_B - 1) / SCAN_B)   // 98

__device__ int    g_counts[N_NODES];
__device__ int    g_cursor[N_NODES];
__device__ int    g_offsets[N_NODES + 1];
__device__ int    g_scantmp[N_NODES];
__device__ int    g_bsums[SCAN_NB];
__device__ int    g_bbase[SCAN_NB];
__device__ int    g_sender[E_TOTAL];            // slot -> sender
__device__ float4 g_rec[(size_t)E_TOTAL * 3];   // slot -> {h0..3, h4..7, ef}
__device__ float4 g_nodes4[N_NODES * 8];        // node -> 8 x {s_m, v_m0, v_m1, v_m2}

__global__ void k_zero_counts() {
    int i = blockIdx.x * blockDim.x + threadIdx.x;
    if (i < N_NODES) g_counts[i] = 0;
}

// Transpose node_feats rows into per-m float4 {s, v0, v1, v2}
__global__ void k_prep_nodes(const float* __restrict__ node_feats) {
    int i = blockIdx.x * blockDim.x + threadIdx.x;   // node*8 + m
    if (i >= N_NODES * 8) return;
    int node = i >> 3;
    int m    = i & 7;
    const float* nf = node_feats + node * 32;
    g_nodes4[i] = make_float4(__ldg(nf + m),
                              __ldg(nf + 8 + 3 * m),
                              __ldg(nf + 9 + 3 * m),
                              __ldg(nf + 10 + 3 * m));
}

__global__ void k_count(const int* __restrict__ receivers) {
    int e = blockIdx.x * blockDim.x + threadIdx.x;
    if (e < E_TOTAL) atomicAdd(&g_counts[__ldg(&receivers[e])], 1);
}

// Pass 1: per-block inclusive scan of counts
__global__ __launch_bounds__(SCAN_B) void k_scan1() {
    __shared__ int sh[SCAN_B];
    int t   = threadIdx.x;
    int idx = blockIdx.x * SCAN_B + t;
    int v   = (idx < N_NODES) ? g_counts[idx] : 0;
    sh[t] = v;
    __syncthreads();
    for (int off = 1; off < SCAN_B; off <<= 1) {
        int u = (t >= off) ? sh[t - off] : 0;
        __syncthreads();
        sh[t] += u;
        __syncthreads();
    }
    if (idx < N_NODES) g_scantmp[idx] = sh[t];
    if (t == SCAN_B - 1) g_bsums[blockIdx.x] = sh[t];
}

// Pass 2: single small block scans the 98 block sums -> exclusive bases
__global__ __launch_bounds__(128) void k_scan2() {
    __shared__ int sh[128];
    int t = threadIdx.x;
    int v = (t < SCAN_NB) ? g_bsums[t] : 0;
    sh[t] = v;
    __syncthreads();
    for (int off = 1; off < 128; off <<= 1) {
        int u = (t >= off) ? sh[t - off] : 0;
        __syncthreads();
        sh[t] += u;
        __syncthreads();
    }
    if (t < SCAN_NB) g_bbase[t] = sh[t] - v;   // exclusive base
    if (t == SCAN_NB - 1) g_offsets[N_NODES] = sh[t];
}

// Pass 3: global exclusive offsets + cursor
__global__ __launch_bounds__(SCAN_B) void k_scan3() {
    int idx = blockIdx.x * SCAN_B + threadIdx.x;
    if (idx < N_NODES) {
        int off = g_bbase[blockIdx.x] + g_scantmp[idx] - g_counts[idx];
        g_offsets[idx] = off;
        g_cursor[idx]  = off;
    }
}

// Fused fill + hidden MLP: coalesced reads in edge order, scattered 52B writes.
__global__ __launch_bounds__(256) void k_fill_hidden(
    const int*    __restrict__ senders,
    const int*    __restrict__ receivers,
    const float4* __restrict__ radial,
    const float4* __restrict__ edge_features,
    const float*  __restrict__ w1)
{
    __shared__ float sw1[64];
    int t = threadIdx.x;
    if (t < 64) sw1[t] = w1[t];
    __syncthreads();

    int e = blockIdx.x * 256 + t;
    if (e >= E_TOTAL) return;

    float4 r0 = __ldg(&radial[2 * e]);
    float4 r1 = __ldg(&radial[2 * e + 1]);
    float4 ef = __ldg(&edge_features[e]);
    int   snd = __ldg(&senders[e]);
    int   rcv = __ldg(&receivers[e]);

    float r[8] = {r0.x, r0.y, r0.z, r0.w, r1.x, r1.y, r1.z, r1.w};
    float h[8];
    #pragma unroll
    for (int j = 0; j < 8; j++) {
        float acc = 0.f;
        #pragma unroll
        for (int i = 0; i < 8; i++) acc = fmaf(r[i], sw1[i * 8 + j], acc);
        h[j] = acc * (FSCALE / (1.f + __expf(-acc)));
    }

    int pos = atomicAdd(&g_cursor[rcv], 1);
    g_sender[pos]        = snd;
    g_rec[3 * pos]       = make_float4(h[0], h[1], h[2], h[3]);
    g_rec[3 * pos + 1]   = make_float4(h[4], h[5], h[6], h[7]);
    g_rec[3 * pos + 2]   = ef;
}

// Block of 128 threads covers 2 nodes: warps 0-1 -> node A, warps 2-3 -> node B.
// Lane l (<24) owns scal[l], vec[l][0..2]. Pointer-increment addressing,
// lane-constant mask FMAs instead of nested SELs.
#define EDGE_BODY(SP, RP)                                                     \
    {                                                                         \
        int snd = *(SP);                                                      \
        float4 nd = g_nodes4[snd * 8 + mm];                                   \
        float4 h0 = (RP)[0];                                                  \
        float4 h1 = (RP)[1];                                                  \
        float4 ef = (RP)[2];                                                  \
        float s = nd.x, v0 = nd.y, v1 = nd.z, v2 = nd.w;                      \
        float e0 = ef.x, e1x = ef.y, e1y = ef.z, e1z = ef.w;                  \
        float wa, wb;                                                         \
        wa = fmaf(h0.x, w2A[0], fmaf(h0.y, w2A[1],                            \
             fmaf(h0.z, w2A[2], h0.w * w2A[3])));                             \
        wa = fmaf(h1.x, w2A[4], fmaf(h1.y, w2A[5],                            \
             fmaf(h1.z, w2A[6], fmaf(h1.w, w2A[7], wa))));                    \
        wb = fmaf(h0.x, w2B[0], fmaf(h0.y, w2B[1],                            \
             fmaf(h0.z, w2B[2], h0.w * w2B[3])));                             \
        wb = fmaf(h1.x, w2B[4], fmaf(h1.y, w2B[5],                            \
             fmaf(h1.z, w2B[6], fmaf(h1.w, w2B[7], wb))));                    \
        float eS = fmaf(mg1, e0, mg0);                                        \
        float fV = fmaf(mg2, e0, mg0);                                        \
        float dot = fmaf(v0, e1x, fmaf(v1, e1y, v2 * e1z));                   \
        float scal_inner = fmaf(s, eS, dot * mg2);                            \
        float sfs = s * mg1;                                                  \
        float i0 = fmaf(v0, fV, sfs * e1x);                                   \
        float i1 = fmaf(v1, fV, sfs * e1y);                                   \
        float i2 = fmaf(v2, fV, sfs * e1z);                                   \
        acc_s  = fmaf(scal_inner, wa, acc_s);                                 \
        acc_v0 = fmaf(i0, wb, acc_v0);                                        \
        acc_v1 = fmaf(i1, wb, acc_v1);                                        \
        acc_v2 = fmaf(i2, wb, acc_v2);                                        \
    }

__global__ __launch_bounds__(128) void k_gather(
    const float* __restrict__ w2,
    float*       __restrict__ out)
{
    __shared__ float red[4][96];

    int lane = threadIdx.x & 31;
    int wi   = threadIdx.x >> 5;   // 0..3
    int sub  = wi >> 1;            // node within block
    int half = wi & 1;             // segment half
    int node = blockIdx.x * 2 + sub;
    int mm   = lane & 7;

    bool g0 = lane < 8;
    bool g1 = (lane >= 8) && (lane < 16);
    bool g2 = (lane >= 16) && (lane < 24);
    int  cA = (lane < 24) ? lane : 0;
    float mg0 = g0 ? 1.f : 0.f;
    float mg1 = g1 ? 1.f : 0.f;
    float mg2 = g2 ? 1.f : 0.f;
    float sA  = g2 ? FINV_SQRT3 : 1.f;

    float w2A[8], w2B[8];
    #pragma unroll
    for (int j = 0; j < 8; j++) {
        w2A[j] = __ldg(&w2[j * 48 + cA]) * sA;
        w2B[j] = __ldg(&w2[j * 48 + 24 + cA]);
    }

    int beg = g_offsets[node];
    int end = g_offsets[node + 1];
    int len = end - beg;
    int lo  = beg + (len * half)       / 2;
    int hi  = beg + (len * (half + 1)) / 2;

    float acc_s = 0.f, acc_v0 = 0.f, acc_v1 = 0.f, acc_v2 = 0.f;

    const int*    sp = g_sender + lo;
    const float4* rp = g_rec + 3 * (size_t)lo;
    int cnt = hi - lo;

    #pragma unroll 1
    while (cnt >= 2) {
        EDGE_BODY(sp, rp)
        EDGE_BODY(sp + 1, rp + 3)
        sp += 2; rp += 6; cnt -= 2;
    }
    if (cnt) EDGE_BODY(sp, rp)

    if (lane < 24) {
        red[wi][lane]              = acc_s;
        red[wi][24 + 3 * lane]     = acc_v0;
        red[wi][24 + 3 * lane + 1] = acc_v1;
        red[wi][24 + 3 * lane + 2] = acc_v2;
    }
    __syncthreads();

    int t = threadIdx.x;
    if (t < 96) {
        size_t ob = (size_t)blockIdx.x * 2 * 96;
        out[ob + t]      = red[0][t] + red[1][t];
        out[ob + 96 + t] = red[2][t] + red[3][t];
    }
}

extern "C" void kernel_launch(void* const* d_in, const int* in_sizes, int n_in,
                              void* d_out, int out_size) {
    const float*  node_feats    = (const float*)d_in[0];
    const float4* edge_features = (const float4*)d_in[1];
    const float4* radial        = (const float4*)d_in[2];
    const float*  w1            = (const float*)d_in[3];
    const float*  w2            = (const float*)d_in[4];
    const int*    senders       = (const int*)d_in[5];
    const int*    receivers     = (const int*)d_in[6];
    float* out = (float*)d_out;

    k_zero_counts<<<(N_NODES + 511) / 512, 512>>>();
    k_prep_nodes<<<(N_NODES * 8 + 255) / 256, 256>>>(node_feats);
    k_count<<<(E_TOTAL + 511) / 512, 512>>>(receivers);
    k_scan1<<<SCAN_NB, SCAN_B>>>();
    k_scan2<<<1, 128>>>();
    k_scan3<<<SCAN_NB, SCAN_B>>>();
    k_fill_hidden<<<(E_TOTAL + 255) / 256, 256>>>(senders, receivers, radial,
                                                  edge_features, w1);
    k_gather<<<N_NODES / 2, 128>>>(w2, out);
}